// round 17
// baseline (speedup 1.0000x reference)
#include <cuda_runtime.h>
#include <cuda_bf16.h>
#include <cstdint>

#define N_NODES 100000
#define N_EDGES 1600000
#define N_FEAT  165
#define HIDDEN  128
#define NEG_SLOPE 0.2f
#define SCAN_BLK 256
#define N_SCAN_BLOCKS ((N_NODES + SCAN_BLK - 1) / SCAN_BLK)   // 391
#define KPAD 176
#define KCHUNK 16
#define NCHUNKS 11

#define GEMM_TOT_BLOCKS 1563   // ceil(100000/64)
#define GEMM_P1 391
#define GEMM_P2 391
#define GEMM_P3 391
#define GEMM_P4 390            // 391*3 + 390 = 1563

// ---------------- scratch (static __device__ arrays; no allocation) -------
__device__ float g_xl[(size_t)N_NODES * HIDDEN];
__device__ float g_xr[(size_t)N_NODES * HIDDEN];
__device__ float g_hl[N_NODES * 2];
__device__ float g_hr[N_NODES * 2];
__device__ int   g_cnt[N_NODES];
__device__ int   g_rowstart[N_NODES + 1];
__device__ int   g_cursor[N_NODES];
__device__ int   g_blocksum[N_SCAN_BLOCKS];
__device__ int   g_csrsrc[N_EDGES];
// bf16 hi/lo planes for W in m16n8k16 fragment order
__device__ unsigned short g_whi[KPAD * 256];
__device__ unsigned short g_wlo[KPAD * 256];

// ---------------- helpers ----------------
__device__ __forceinline__ float warpSum(float v) {
    #pragma unroll
    for (int o = 16; o > 0; o >>= 1) v += __shfl_xor_sync(0xffffffffu, v, o);
    return v;
}

__device__ __forceinline__ void warpSum2(float& a, float& b) {
    #pragma unroll
    for (int o = 16; o > 0; o >>= 1) {
        a += __shfl_xor_sync(0xffffffffu, a, o);
        b += __shfl_xor_sync(0xffffffffu, b, o);
    }
}

__device__ __forceinline__ void warpSum4(float& a, float& b, float& c, float& d) {
    #pragma unroll
    for (int o = 16; o > 0; o >>= 1) {
        a += __shfl_xor_sync(0xffffffffu, a, o);
        b += __shfl_xor_sync(0xffffffffu, b, o);
        c += __shfl_xor_sync(0xffffffffu, c, o);
        d += __shfl_xor_sync(0xffffffffu, d, o);
    }
}

__device__ __forceinline__ float lrelu(float v) {
    return v > 0.f ? v : NEG_SLOPE * v;
}

__device__ __forceinline__ float dot_lrelu(float4 a, float4 b, float4 t) {
    return lrelu(a.x + b.x) * t.x + lrelu(a.y + b.y) * t.y
         + lrelu(a.z + b.z) * t.z + lrelu(a.w + b.w) * t.w;
}

__device__ __forceinline__ uint32_t s2u(const void* p) {
    return (uint32_t)__cvta_generic_to_shared(p);
}
#define CPA4(d, s)  asm volatile("cp.async.ca.shared.global [%0], [%1], 4;"  :: "r"(d), "l"(s))
#define CPA16(d, s) asm volatile("cp.async.cg.shared.global [%0], [%1], 16;" :: "r"(d), "l"(s))
#define CP_COMMIT() asm volatile("cp.async.commit_group;" ::: "memory")
#define CP_WAIT1()  asm volatile("cp.async.wait_group 1;" ::: "memory")
#define CP_WAIT0()  asm volatile("cp.async.wait_group 0;" ::: "memory")

// bf16x3 split: lo_v = element k (lower half), hi_v = element k+1 (upper half)
__device__ __forceinline__ void packsplit(float lo_v, float hi_v,
                                          uint32_t& hp, uint32_t& lp) {
    asm("cvt.rn.bf16x2.f32 %0, %1, %2;" : "=r"(hp) : "f"(hi_v), "f"(lo_v));
    float h_lo = __uint_as_float(hp << 16);
    float h_hi = __uint_as_float(hp & 0xffff0000u);
    float r_lo = lo_v - h_lo;
    float r_hi = hi_v - h_hi;
    asm("cvt.rn.bf16x2.f32 %0, %1, %2;" : "=r"(lp) : "f"(r_hi), "f"(r_lo));
}

#define MMA_BF16(D, A, b0, b1) \
    asm volatile("mma.sync.aligned.m16n8k16.row.col.f32.bf16.bf16.f32 " \
        "{%0,%1,%2,%3}, {%4,%5,%6,%7}, {%8,%9}, {%0,%1,%2,%3};" \
        : "+f"((D)[0]), "+f"((D)[1]), "+f"((D)[2]), "+f"((D)[3]) \
        : "r"((A)[0]), "r"((A)[1]), "r"((A)[2]), "r"((A)[3]), "r"(b0), "r"(b1))

// ================= bf16 hi/lo split for W + g_cnt zeroing ==================
__global__ void split_w(const float* __restrict__ W1l, const float* __restrict__ W1r) {
    int i = blockIdx.x * blockDim.x + threadIdx.x;
    if (i < N_NODES) g_cnt[i] = 0;
    if (i >= KPAD * 256) return;
    int k = i >> 8, n = i & 255;
    float v = 0.f;
    if (k < N_FEAT) v = (n < 128) ? W1l[k * HIDDEN + n] : W1r[k * HIDDEN + (n - 128)];
    __nv_bfloat16 hb = __float2bfloat16_rn(v);
    unsigned short h = __bfloat16_as_ushort(hb);
    float hf = __uint_as_float((uint32_t)h << 16);
    float r = v - hf;
    unsigned short lo = __bfloat16_as_ushort(__float2bfloat16_rn(r));

    int c    = k >> 4;
    int kr   = k & 15;
    int tig  = (kr >> 1) & 3;
    int bslot = kr >> 3;
    int lh   = kr & 1;
    int nt   = n >> 4;
    int nn   = n & 15;
    int gg   = nn & 7;
    int jh   = nn >> 3;
    int lane = gg * 4 + tig;
    int q    = jh * 2 + bslot;
    size_t word = (((size_t)c * 16 + nt) * 32 + lane) * 4 + q;
    g_whi[word * 2 + lh] = h;
    g_wlo[word * 2 + lh] = lo;
}

// ================= GEMM body (device function; bid = virtual block id) =====
__device__ void gemm_body(int bid, const float* __restrict__ Xp,
                          const float* __restrict__ b1l,
                          const float* __restrict__ b1r,
                          float* dsm) {
    float* XS = dsm;                             // [stg][64][20]
    uint32_t* WS = (uint32_t*)(dsm + 2560);      // [stg][pl][2048 words]

    const int tid = threadIdx.x;
    const int wid = tid >> 5;
    const int lane = tid & 31;
    const int g   = lane >> 2;
    const int tig = lane & 3;
    const int wm = wid >> 2;
    const int wn = wid & 3;
    const int row0 = bid * 64;

    auto xs_s  = [&](int stg) { return XS + stg * 1280; };
    auto ws_pl = [&](int stg, int pl) { return WS + (stg * 2 + pl) * 2048; };

    auto load_chunk = [&](int c, int stg) {
        int k0 = c * KCHUNK;
        float* xbase = xs_s(stg);
        #pragma unroll
        for (int i = 0; i < 4; i++) {
            int lin = tid + i * 256;
            int m = lin >> 4, k = lin & 15;
            int gr = row0 + m, gk = k0 + k;
            float* dstp = xbase + m * 20 + k;
            if (gr < N_NODES && gk < N_FEAT)
                CPA4(s2u(dstp), Xp + (size_t)gr * N_FEAT + gk);
            else
                *dstp = 0.f;
        }
        const uint32_t* gw0 = (const uint32_t*)g_whi;
        const uint32_t* gw1 = (const uint32_t*)g_wlo;
        const size_t gbase = (size_t)c * 2048;
        uint32_t* w0 = ws_pl(stg, 0);
        uint32_t* w1 = ws_pl(stg, 1);
        #pragma unroll
        for (int i = 0; i < 2; i++) {
            int L = (tid + i * 256) * 4;
            CPA16(s2u(w0 + L), gw0 + gbase + L);
            CPA16(s2u(w1 + L), gw1 + gbase + L);
        }
    };

    float d[2][8][4];
    #pragma unroll
    for (int i = 0; i < 2; i++)
        #pragma unroll
        for (int j = 0; j < 8; j++)
            #pragma unroll
            for (int q = 0; q < 4; q++) d[i][j][q] = 0.f;

    load_chunk(0, 0);
    CP_COMMIT();

    for (int c = 0; c < NCHUNKS; c++) {
        int stg = c & 1;
        if (c + 1 < NCHUNKS) {
            load_chunk(c + 1, (c + 1) & 1);
            CP_COMMIT();
            CP_WAIT1();
        } else {
            CP_WAIT0();
        }
        __syncthreads();

        const float* xs = xs_s(stg);
        const uint4* whi4 = (const uint4*)ws_pl(stg, 0);
        const uint4* wlo4 = (const uint4*)ws_pl(stg, 1);

        uint32_t ahi[2][4], alo[2][4];
        #pragma unroll
        for (int i = 0; i < 2; i++) {
            int rb = wm * 32 + i * 16;
            const float* r0p = xs + (rb + g) * 20 + 2 * tig;
            const float* r1p = xs + (rb + g + 8) * 20 + 2 * tig;
            float2 x0 = *(const float2*)r0p;
            float2 x1 = *(const float2*)r1p;
            float2 x2 = *(const float2*)(r0p + 8);
            float2 x3 = *(const float2*)(r1p + 8);
            packsplit(x0.x, x0.y, ahi[i][0], alo[i][0]);
            packsplit(x1.x, x1.y, ahi[i][1], alo[i][1]);
            packsplit(x2.x, x2.y, ahi[i][2], alo[i][2]);
            packsplit(x3.x, x3.y, ahi[i][3], alo[i][3]);
        }

        uint4 BH[4], BL[4];
        #pragma unroll
        for (int jp = 0; jp < 4; jp++) {
            int idx = (wn * 4 + jp) * 32 + lane;
            BH[jp] = whi4[idx];
            BL[jp] = wlo4[idx];
        }

        #pragma unroll
        for (int jp = 0; jp < 4; jp++)
            #pragma unroll
            for (int i = 0; i < 2; i++) {
                MMA_BF16(d[i][jp * 2],     ahi[i], BH[jp].x, BH[jp].y);
                MMA_BF16(d[i][jp * 2 + 1], ahi[i], BH[jp].z, BH[jp].w);
            }
        #pragma unroll
        for (int jp = 0; jp < 4; jp++)
            #pragma unroll
            for (int i = 0; i < 2; i++) {
                MMA_BF16(d[i][jp * 2],     ahi[i], BL[jp].x, BL[jp].y);
                MMA_BF16(d[i][jp * 2 + 1], ahi[i], BL[jp].z, BL[jp].w);
            }
        #pragma unroll
        for (int jp = 0; jp < 4; jp++)
            #pragma unroll
            for (int i = 0; i < 2; i++) {
                MMA_BF16(d[i][jp * 2],     alo[i], BH[jp].x, BH[jp].y);
                MMA_BF16(d[i][jp * 2 + 1], alo[i], BH[jp].z, BH[jp].w);
            }
        __syncthreads();
    }

    #pragma unroll
    for (int i = 0; i < 2; i++) {
        int r0 = row0 + wm * 32 + i * 16 + g;
        int r1 = r0 + 8;
        #pragma unroll
        for (int j = 0; j < 8; j++) {
            int col = wn * 64 + j * 8 + tig * 2;
            if (col < 128) {
                float bb0 = __ldg(&b1l[col]), bb1 = __ldg(&b1l[col + 1]);
                if (r0 < N_NODES) {
                    float2 v = make_float2(d[i][j][0] + bb0, d[i][j][1] + bb1);
                    *(float2*)(g_xl + (size_t)r0 * HIDDEN + col) = v;
                }
                if (r1 < N_NODES) {
                    float2 v = make_float2(d[i][j][2] + bb0, d[i][j][3] + bb1);
                    *(float2*)(g_xl + (size_t)r1 * HIDDEN + col) = v;
                }
            } else {
                int c2 = col - 128;
                float bb0 = __ldg(&b1r[c2]), bb1 = __ldg(&b1r[c2 + 1]);
                if (r0 < N_NODES) {
                    float2 v = make_float2(d[i][j][0] + bb0, d[i][j][1] + bb1);
                    *(float2*)(g_xr + (size_t)r0 * HIDDEN + c2) = v;
                }
                if (r1 < N_NODES) {
                    float2 v = make_float2(d[i][j][2] + bb0, d[i][j][3] + bb1);
                    *(float2*)(g_xr + (size_t)r1 * HIDDEN + c2) = v;
                }
            }
        }
    }
}

// ================= CSR bodies =================
__device__ void scan1_body(int b, int* sh) {
    int t = threadIdx.x;
    int i = b * SCAN_BLK + t;
    int v = (i < N_NODES) ? g_cnt[i] : 0;
    sh[t] = v;
    __syncthreads();
    #pragma unroll
    for (int off = 1; off < SCAN_BLK; off <<= 1) {
        int add = (t >= off) ? sh[t - off] : 0;
        __syncthreads();
        sh[t] += add;
        __syncthreads();
    }
    if (i < N_NODES) g_rowstart[i] = sh[t] - v;
    if (t == SCAN_BLK - 1) g_blocksum[b] = sh[t];
}

// scan of 391 block sums, 256 threads handling 2 virtual slots each
__device__ void scan2_body(int* sh) {
    int t = threadIdx.x;
    int v0 = (t < N_SCAN_BLOCKS) ? g_blocksum[t] : 0;
    int v1 = (t + 256 < N_SCAN_BLOCKS) ? g_blocksum[t + 256] : 0;
    sh[t] = v0;
    sh[t + 256] = v1;
    __syncthreads();
    #pragma unroll
    for (int off = 1; off < 512; off <<= 1) {
        int a = (t >= off) ? sh[t - off] : 0;
        int b = (t + 256 >= off) ? sh[t + 256 - off] : 0;
        __syncthreads();
        sh[t] += a;
        sh[t + 256] += b;
        __syncthreads();
    }
    if (t < N_SCAN_BLOCKS) g_blocksum[t] = sh[t] - v0;
    if (t + 256 < N_SCAN_BLOCKS) g_blocksum[t + 256] = sh[t + 256] - v1;
}

__global__ void csr_scan3() {
    int i = blockIdx.x * blockDim.x + threadIdx.x;
    if (i < N_NODES) {
        int rs = g_rowstart[i] + g_blocksum[i / SCAN_BLK];
        g_rowstart[i] = rs;
        g_cursor[i] = rs;
    }
    if (i == 0) g_rowstart[N_NODES] = N_EDGES;
}

// ================= fused kernels: gemm chunk + CSR stage ==================
__global__ void __launch_bounds__(256, 2) fused1(const float* __restrict__ Xp,
                                                 const float* __restrict__ b1l,
                                                 const float* __restrict__ b1r,
                                                 const int* __restrict__ dst) {
    extern __shared__ float dsm[];
    if (blockIdx.x < GEMM_P1) {
        gemm_body(blockIdx.x, Xp, b1l, b1r, dsm);
    } else {
        int e = (blockIdx.x - GEMM_P1) * 256 + threadIdx.x;
        if (e < N_EDGES) atomicAdd(&g_cnt[dst[e]], 1);
    }
}

__global__ void __launch_bounds__(256, 2) fused2(const float* __restrict__ Xp,
                                                 const float* __restrict__ b1l,
                                                 const float* __restrict__ b1r) {
    extern __shared__ float dsm[];
    if (blockIdx.x < GEMM_P2) {
        gemm_body(GEMM_P1 + blockIdx.x, Xp, b1l, b1r, dsm);
    } else {
        scan1_body(blockIdx.x - GEMM_P2, (int*)dsm);
    }
}

__global__ void __launch_bounds__(256, 2) fused3(const float* __restrict__ Xp,
                                                 const float* __restrict__ b1l,
                                                 const float* __restrict__ b1r) {
    extern __shared__ float dsm[];
    if (blockIdx.x < GEMM_P3) {
        gemm_body(GEMM_P1 + GEMM_P2 + blockIdx.x, Xp, b1l, b1r, dsm);
    } else {
        scan2_body((int*)dsm);     // single extra block
    }
}

__global__ void __launch_bounds__(256, 2) fused4(const float* __restrict__ Xp,
                                                 const float* __restrict__ b1l,
                                                 const float* __restrict__ b1r,
                                                 const int* __restrict__ src,
                                                 const int* __restrict__ dst) {
    extern __shared__ float dsm[];
    if (blockIdx.x < GEMM_P4) {
        gemm_body(GEMM_P1 + GEMM_P2 + GEMM_P3 + blockIdx.x, Xp, b1l, b1r, dsm);
    } else {
        int e = (blockIdx.x - GEMM_P4) * 256 + threadIdx.x;
        if (e < N_EDGES) {
            int pos = atomicAdd(&g_cursor[dst[e]], 1);
            g_csrsrc[pos] = src[e];
        }
    }
}

// ================= layer 1: warp-per-node, 4-wide edge unroll ==============
__global__ void __launch_bounds__(256) layer1_csr(const float* __restrict__ att,
                                                  const float* __restrict__ bias1,
                                                  const float* __restrict__ W2l,
                                                  const float* __restrict__ b2l,
                                                  const float* __restrict__ W2r,
                                                  const float* __restrict__ b2r) {
    int d = (blockIdx.x * blockDim.x + threadIdx.x) >> 5;
    int lane = threadIdx.x & 31;
    if (d >= N_NODES) return;

    float4 xr4  = ((const float4*)(g_xr + (size_t)d * HIDDEN))[lane];
    float4 att4 = __ldg(&((const float4*)att)[lane]);

    float4 xls = ((const float4*)(g_xl + (size_t)d * HIDDEN))[lane];
    float p = warpSum(dot_lrelu(xls, xr4, att4));
    float w = __expf(p);
    float wsum = w;
    float4 acc = make_float4(w * xls.x, w * xls.y, w * xls.z, w * xls.w);

    int j  = g_rowstart[d];
    int re = g_rowstart[d + 1];

    for (; j + 3 < re; j += 4) {
        int s0 = g_csrsrc[j],     s1 = g_csrsrc[j + 1];
        int s2 = g_csrsrc[j + 2], s3 = g_csrsrc[j + 3];
        float4 a0 = ((const float4*)(g_xl + (size_t)s0 * HIDDEN))[lane];
        float4 a1 = ((const float4*)(g_xl + (size_t)s1 * HIDDEN))[lane];
        float4 a2 = ((const float4*)(g_xl + (size_t)s2 * HIDDEN))[lane];
        float4 a3 = ((const float4*)(g_xl + (size_t)s3 * HIDDEN))[lane];
        float p0 = dot_lrelu(a0, xr4, att4);
        float p1 = dot_lrelu(a1, xr4, att4);
        float p2 = dot_lrelu(a2, xr4, att4);
        float p3 = dot_lrelu(a3, xr4, att4);
        warpSum4(p0, p1, p2, p3);
        float w0 = __expf(p0), w1 = __expf(p1);
        float w2 = __expf(p2), w3 = __expf(p3);
        wsum += (w0 + w1) + (w2 + w3);
        acc.x += w0 * a0.x + w1 * a1.x + w2 * a2.x + w3 * a3.x;
        acc.y += w0 * a0.y + w1 * a1.y + w2 * a2.y + w3 * a3.y;
        acc.z += w0 * a0.z + w1 * a1.z + w2 * a2.z + w3 * a3.z;
        acc.w += w0 * a0.w + w1 * a1.w + w2 * a2.w + w3 * a3.w;
    }
    for (; j + 1 < re; j += 2) {
        int s0 = g_csrsrc[j], s1 = g_csrsrc[j + 1];
        float4 a0 = ((const float4*)(g_xl + (size_t)s0 * HIDDEN))[lane];
        float4 a1 = ((const float4*)(g_xl + (size_t)s1 * HIDDEN))[lane];
        float p0 = dot_lrelu(a0, xr4, att4);
        float p1 = dot_lrelu(a1, xr4, att4);
        warpSum2(p0, p1);
        float w0 = __expf(p0), w1 = __expf(p1);
        wsum += w0 + w1;
        acc.x += w0 * a0.x + w1 * a1.x;
        acc.y += w0 * a0.y + w1 * a1.y;
        acc.z += w0 * a0.z + w1 * a1.z;
        acc.w += w0 * a0.w + w1 * a1.w;
    }
    if (j < re) {
        int s0 = g_csrsrc[j];
        float4 a0 = ((const float4*)(g_xl + (size_t)s0 * HIDDEN))[lane];
        float w0 = __expf(warpSum(dot_lrelu(a0, xr4, att4)));
        wsum += w0;
        acc.x += w0 * a0.x; acc.y += w0 * a0.y;
        acc.z += w0 * a0.z; acc.w += w0 * a0.w;
    }

    float inv = __fdividef(1.f, wsum);
    float4 b4 = __ldg(&((const float4*)bias1)[lane]);
    float h0 = acc.x * inv + b4.x;  h0 = h0 > 0.f ? h0 : 0.f;
    float h1 = acc.y * inv + b4.y;  h1 = h1 > 0.f ? h1 : 0.f;
    float h2 = acc.z * inv + b4.z;  h2 = h2 > 0.f ? h2 : 0.f;
    float h3 = acc.w * inv + b4.w;  h3 = h3 > 0.f ? h3 : 0.f;

    float4 wl0 = __ldg(&((const float4*)W2l)[2 * lane]);
    float4 wl1 = __ldg(&((const float4*)W2l)[2 * lane + 1]);
    float4 wr0 = __ldg(&((const float4*)W2r)[2 * lane]);
    float4 wr1 = __ldg(&((const float4*)W2r)[2 * lane + 1]);

    float s0 = h0 * wl0.x + h1 * wl0.z + h2 * wl1.x + h3 * wl1.z;
    float s1 = h0 * wl0.y + h1 * wl0.w + h2 * wl1.y + h3 * wl1.w;
    float s2 = h0 * wr0.x + h1 * wr0.z + h2 * wr1.x + h3 * wr1.z;
    float s3 = h0 * wr0.y + h1 * wr0.w + h2 * wr1.y + h3 * wr1.w;
    warpSum4(s0, s1, s2, s3);

    if (lane == 0) {
        g_hl[2 * d + 0] = s0 + __ldg(&b2l[0]);
        g_hl[2 * d + 1] = s1 + __ldg(&b2l[1]);
        g_hr[2 * d + 0] = s2 + __ldg(&b2r[0]);
        g_hr[2 * d + 1] = s3 + __ldg(&b2r[1]);
    }
}

// ================= layer 2: 8 lanes/node, 4 nodes/warp ====================
__global__ void __launch_bounds__(256) layer2_csr(const float* __restrict__ att2,
                                                  const float* __restrict__ bias2,
                                                  float* __restrict__ out) {
    int t = blockIdx.x * blockDim.x + threadIdx.x;
    int d = t >> 3;
    int gl = t & 7;
    if (d >= N_NODES) return;

    float a20 = __ldg(&att2[0]);
    float a21 = __ldg(&att2[1]);
    float2 hr2 = *(const float2*)(g_hr + 2 * d);

    float den = 0.f, n0 = 0.f, n1 = 0.f;

    if (gl == 0) {
        float2 hls = *(const float2*)(g_hl + 2 * d);
        float sc = lrelu(hls.x + hr2.x) * a20 + lrelu(hls.y + hr2.y) * a21;
        float w = __expf(sc);
        den = w; n0 = w * hls.x; n1 = w * hls.y;
    }

    int rs = g_rowstart[d];
    int re = g_rowstart[d + 1];
    for (int j = rs + gl; j < re; j += 8) {
        int s = g_csrsrc[j];
        float2 hl = *(const float2*)(g_hl + 2 * s);
        float sc = lrelu(hl.x + hr2.x) * a20 + lrelu(hl.y + hr2.y) * a21;
        float w = __expf(sc);
        den += w; n0 += w * hl.x; n1 += w * hl.y;
    }

    #pragma unroll
    for (int o = 1; o < 8; o <<= 1) {
        den += __shfl_xor_sync(0xffffffffu, den, o);
        n0  += __shfl_xor_sync(0xffffffffu, n0, o);
        n1  += __shfl_xor_sync(0xffffffffu, n1, o);
    }

    if (gl == 0) {
        float inv = __fdividef(1.f, den);
        out[2 * d + 0] = n0 * inv + __ldg(&bias2[0]);
        out[2 * d + 1] = n1 * inv + __ldg(&bias2[1]);
    }
}

// ---------------- launch ----------------
extern "C" void kernel_launch(void* const* d_in, const int* in_sizes, int n_in,
                              void* d_out, int out_size) {
    const float* x    = (const float*)d_in[0];
    const int*   src  = (const int*)  d_in[1];
    const int*   dst  = (const int*)  d_in[2];
    const float* W1l  = (const float*)d_in[3];
    const float* b1l  = (const float*)d_in[4];
    const float* W1r  = (const float*)d_in[5];
    const float* b1r  = (const float*)d_in[6];
    const float* att1 = (const float*)d_in[7];
    const float* bias1= (const float*)d_in[8];
    const float* W2l  = (const float*)d_in[9];
    const float* b2l  = (const float*)d_in[10];
    const float* W2r  = (const float*)d_in[11];
    const float* b2r  = (const float*)d_in[12];
    const float* att2 = (const float*)d_in[13];
    const float* bias2= (const float*)d_in[14];
    float* out = (float*)d_out;

    const int edgeBlocks = (N_EDGES + 255) / 256;             // 6250
    const int nodeBlocks = (N_NODES + 255) / 256;             // 391
    const int nodeWarpBlocks = (N_NODES * 32 + 255) / 256;    // 12500
    const int node8Blocks = (N_NODES * 8 + 255) / 256;        // 3125
    const int GEMM_SMEM = 2560 * 4 + 4 * 2048 * 4;            // 43008 B

    cudaFuncSetAttribute((const void*)fused1,
                         cudaFuncAttributeMaxDynamicSharedMemorySize, GEMM_SMEM);
    cudaFuncSetAttribute((const void*)fused2,
                         cudaFuncAttributeMaxDynamicSharedMemorySize, GEMM_SMEM);
    cudaFuncSetAttribute((const void*)fused3,
                         cudaFuncAttributeMaxDynamicSharedMemorySize, GEMM_SMEM);
    cudaFuncSetAttribute((const void*)fused4,
                         cudaFuncAttributeMaxDynamicSharedMemorySize, GEMM_SMEM);

    split_w<<<nodeBlocks, 256>>>(W1l, W1r);                        // + g_cnt = 0
    fused1<<<GEMM_P1 + edgeBlocks, 256, GEMM_SMEM>>>(x, b1l, b1r, dst);      // gemmA + hist
    fused2<<<GEMM_P2 + N_SCAN_BLOCKS, 256, GEMM_SMEM>>>(x, b1l, b1r);        // gemmB + scan1
    fused3<<<GEMM_P3 + 1, 256, GEMM_SMEM>>>(x, b1l, b1r);                    // gemmC + scan2
    csr_scan3<<<nodeBlocks, 256>>>();
    fused4<<<GEMM_P4 + edgeBlocks, 256, GEMM_SMEM>>>(x, b1l, b1r, src, dst); // gemmD + scatter
    layer1_csr<<<nodeWarpBlocks, 256>>>(att1, bias1, W2l, b2l, W2r, b2r);
    layer2_csr<<<node8Blocks, 256>>>(att2, bias2, out);
}